// round 3
// baseline (speedup 1.0000x reference)
#include <cuda_runtime.h>
#include <cuda_bf16.h>

// ---------------------------------------------------------------------------
// CavAttention fused kernel (Round 1: fp32 SIMT baseline, fully fused)
//
// Shapes: x (B=2, L=5, H=48, W=176, C=256), HEADS=8, DHEAD=32, INNER=256.
// One CTA processes GPB=16 (b,h,w) groups = 80 tokens end-to-end:
//   1) load x slab [80,256] to smem
//   2) per head: GEMM [80,256]x[256,96] -> q|k|v slab; masked softmax over L=5;
//      P@V accumulated into attention-output slab [80,256] in smem
//   3) output GEMM [80,256]x[256,256] + bias, transposed store to (B,L,H,W,C)
// ---------------------------------------------------------------------------

#define B_     2
#define L_     5
#define H_     48
#define W_     176
#define C_     256
#define HEADS_ 8
#define DHEAD_ 32
#define INNER_ 256
#define NQKV_  768
#define HW_    (H_ * W_)        // 8448
#define NGROUPS_ (B_ * HW_)     // 16896

#define GPB    16               // groups per block
#define MROWS  (GPB * L_)       // 80 tokens per block
#define NTHREADS 256
#define NBLOCKS (NGROUPS_ / GPB) // 1056

#define XS_STRIDE  257          // pad 256 -> 257 (conflict-free column reads)
#define QKV_STRIDE 100          // pad 96 -> 100
#define WB_STRIDE  132          // pad 128 -> 132 (gemm2); gemm1 uses stride 100

// shared memory layout (floats)
#define XS_ELEMS   (MROWS * XS_STRIDE)    // 20560
#define OS_ELEMS   (MROWS * XS_STRIDE)    // 20560
#define QKV_ELEMS  (MROWS * QKV_STRIDE)   // 8000
#define WB_ELEMS   (32 * WB_STRIDE)       // 4224
#define SC_ELEMS   (GPB * 25)             // 400
#define MS_ELEMS   (GPB * L_)             // 80 (ints)
#define SMEM_FLOATS (XS_ELEMS + OS_ELEMS + QKV_ELEMS + WB_ELEMS + SC_ELEMS)
#define SMEM_BYTES  (SMEM_FLOATS * 4 + MS_ELEMS * 4)   // 215,296 B

__global__ __launch_bounds__(NTHREADS, 1)
void cav_attention_fused(const float* __restrict__ x,
                         const int*   __restrict__ mask,
                         const float* __restrict__ wqkv,
                         const float* __restrict__ wout,
                         const float* __restrict__ bout,
                         float*       __restrict__ out) {
    extern __shared__ float sm[];
    float* xs   = sm;                         // [80][257] input tokens
    float* os   = xs + XS_ELEMS;              // [80][257] attention output
    float* qkvh = os + OS_ELEMS;              // [80][100] per-head q|k|v
    float* wb   = qkvh + QKV_ELEMS;           // [32][<=132] staged weights
    float* sc   = wb + WB_ELEMS;              // [16][5][5] scores/probs
    int*   ms   = (int*)(sc + SC_ELEMS);      // [16][5] mask

    const int tid = threadIdx.x;
    const int tx  = tid & 15;                 // N direction (16)
    const int ty  = tid >> 4;                 // M direction (16)
    const int g0  = blockIdx.x * GPB;

    // ---- load mask for the 16 groups: mask layout (B,H,W,1,L) = [g][j] ----
    for (int e = tid; e < GPB * L_; e += NTHREADS) {
        int g = g0 + e / L_;
        int j = e % L_;
        ms[e] = mask[g * L_ + j];
    }

    // ---- load x tokens: row = g_local*5 + l ; x flat = ((b*L+l)*HW + hw)*C + c
    for (int e = tid; e < MROWS * (C_ / 4); e += NTHREADS) {
        int row = e / (C_ / 4);
        int c4  = (e % (C_ / 4)) * 4;
        int g   = g0 + row / L_;
        int l   = row % L_;
        int b   = g / HW_;
        int hw  = g % HW_;
        const float4 v = *(const float4*)(x + ((size_t)((b * L_ + l) * HW_ + hw)) * C_ + c4);
        float* dst = xs + row * XS_STRIDE + c4;
        dst[0] = v.x; dst[1] = v.y; dst[2] = v.z; dst[3] = v.w;
    }
    __syncthreads();

    const float scale = 0.17677669529663687f;  // 1/sqrt(32)

    // hoisted row pointers for the M tiles (rows ty, ty+16, ..., ty+64)
    const float* xrow[5];
    #pragma unroll
    for (int i = 0; i < 5; ++i) xrow[i] = xs + (ty + 16 * i) * XS_STRIDE;
    const float* orow[5];
    #pragma unroll
    for (int i = 0; i < 5; ++i) orow[i] = os + (ty + 16 * i) * XS_STRIDE;

    // ======================= per-head QKV GEMM + attention ==================
    for (int head = 0; head < HEADS_; ++head) {
        float acc[5][6];
        #pragma unroll
        for (int i = 0; i < 5; ++i)
            #pragma unroll
            for (int j = 0; j < 6; ++j) acc[i][j] = 0.f;

        for (int k0 = 0; k0 < C_; k0 += 32) {
            // stage 32 x 96 weight tile: cols {q,k,v} for this head
            for (int e = tid; e < 32 * 96; e += NTHREADS) {
                int kk = e / 96, n = e % 96;
                int part = n >> 5;                       // 0:q 1:k 2:v
                int col  = part * INNER_ + head * DHEAD_ + (n & 31);
                wb[kk * QKV_STRIDE + n] = wqkv[(k0 + kk) * NQKV_ + col];
            }
            __syncthreads();

            #pragma unroll 8
            for (int kk = 0; kk < 32; ++kk) {
                float a[5], bv[6];
                #pragma unroll
                for (int i = 0; i < 5; ++i) a[i] = xrow[i][k0 + kk];
                const float* wr = wb + kk * QKV_STRIDE + tx;
                #pragma unroll
                for (int j = 0; j < 6; ++j) bv[j] = wr[16 * j];
                #pragma unroll
                for (int i = 0; i < 5; ++i)
                    #pragma unroll
                    for (int j = 0; j < 6; ++j)
                        acc[i][j] = fmaf(a[i], bv[j], acc[i][j]);
            }
            __syncthreads();
        }

        // write q|k|v slab
        #pragma unroll
        for (int i = 0; i < 5; ++i)
            #pragma unroll
            for (int j = 0; j < 6; ++j)
                qkvh[(ty + 16 * i) * QKV_STRIDE + tx + 16 * j] = acc[i][j];
        __syncthreads();

        // ---- scores: s[g][i][j] = scale * q_i . k_j  (masked) ----
        for (int e = tid; e < GPB * 25; e += NTHREADS) {
            int g = e / 25, r = e % 25, i = r / 5, j = r % 5;
            float s;
            if (ms[g * 5 + j] == 0) {
                s = -1e30f;
            } else {
                const float* qr = qkvh + (g * 5 + i) * QKV_STRIDE;
                const float* kr = qkvh + (g * 5 + j) * QKV_STRIDE + 32;
                s = 0.f;
                #pragma unroll
                for (int d = 0; d < 32; ++d) s = fmaf(qr[d], kr[d], s);
                s *= scale;
            }
            sc[e] = s;
        }
        __syncthreads();

        // ---- softmax over j per (g,i): 80 rows ----
        if (tid < MROWS) {
            int g = tid / 5, i = tid % 5;
            float* r = sc + g * 25 + i * 5;
            float mx = r[0];
            #pragma unroll
            for (int j = 1; j < 5; ++j) mx = fmaxf(mx, r[j]);
            float ev[5], s = 0.f;
            #pragma unroll
            for (int j = 0; j < 5; ++j) { ev[j] = __expf(r[j] - mx); s += ev[j]; }
            float inv = 1.f / s;
            #pragma unroll
            for (int j = 0; j < 5; ++j) r[j] = ev[j] * inv;
        }
        __syncthreads();

        // ---- o[row][d] = sum_j p * v_j[d], stored at column head*32+d ----
        for (int e = tid; e < MROWS * DHEAD_; e += NTHREADS) {
            int row = e >> 5, d = e & 31;
            int g = row / 5, i = row % 5;
            const float* p = sc + g * 25 + i * 5;
            float o = 0.f;
            #pragma unroll
            for (int j = 0; j < 5; ++j)
                o = fmaf(p[j], qkvh[(g * 5 + j) * QKV_STRIDE + 64 + d], o);
            os[row * XS_STRIDE + head * DHEAD_ + d] = o;
        }
        __syncthreads();   // qkvh reused next head
    }

    // ======================= output GEMM + bias + transposed store ==========
    for (int nc = 0; nc < 2; ++nc) {               // two 128-col chunks
        float acc[5][8];
        #pragma unroll
        for (int i = 0; i < 5; ++i)
            #pragma unroll
            for (int j = 0; j < 8; ++j) acc[i][j] = 0.f;

        for (int k0 = 0; k0 < C_; k0 += 32) {
            for (int e = tid; e < 32 * 128; e += NTHREADS) {
                int kk = e >> 7, n = e & 127;
                wb[kk * WB_STRIDE + n] = wout[(k0 + kk) * INNER_ + nc * 128 + n];
            }
            __syncthreads();

            #pragma unroll 8
            for (int kk = 0; kk < 32; ++kk) {
                float a[5], bv[8];
                #pragma unroll
                for (int i = 0; i < 5; ++i) a[i] = orow[i][k0 + kk];
                const float* wr = wb + kk * WB_STRIDE + tx;
                #pragma unroll
                for (int j = 0; j < 8; ++j) bv[j] = wr[16 * j];
                #pragma unroll
                for (int i = 0; i < 5; ++i)
                    #pragma unroll
                    for (int j = 0; j < 8; ++j)
                        acc[i][j] = fmaf(a[i], bv[j], acc[i][j]);
            }
            __syncthreads();
        }

        // epilogue: out flat = ((b*L+l)*HW + hw)*C + col  (same layout as x)
        #pragma unroll
        for (int i = 0; i < 5; ++i) {
            int row = ty + 16 * i;
            int g   = g0 + row / 5;
            int l   = row % 5;
            int b   = g / HW_;
            int hw  = g % HW_;
            size_t base = ((size_t)((b * L_ + l) * HW_ + hw)) * C_;
            #pragma unroll
            for (int j = 0; j < 8; ++j) {
                int col = nc * 128 + tx + 16 * j;
                out[base + col] = acc[i][j] + bout[col];
            }
        }
    }
}

extern "C" void kernel_launch(void* const* d_in, const int* in_sizes, int n_in,
                              void* d_out, int out_size) {
    const float* x    = (const float*)d_in[0];
    const int*   mask = (const int*)d_in[1];
    const float* wqkv = (const float*)d_in[2];
    const float* wout = (const float*)d_in[3];
    const float* bout = (const float*)d_in[4];
    float*       out  = (float*)d_out;

    cudaFuncSetAttribute(cav_attention_fused,
                         cudaFuncAttributeMaxDynamicSharedMemorySize, SMEM_BYTES);
    cav_attention_fused<<<NBLOCKS, NTHREADS, SMEM_BYTES>>>(x, mask, wqkv, wout, bout, out);
}

// round 5
// speedup vs baseline: 2.0261x; 2.0261x over previous
#include <cuda_runtime.h>
#include <cuda_bf16.h>
#include <stdint.h>

// ===========================================================================
// CavAttention via mma.sync bf16 hi/lo split precision (3 passes)
//   prep: wqkv/wout -> bf16 hi/lo global images (padded pitch 136)
//   K1:   qkv = xp @ wqkv                 (HMMA)  -> g_qkv
//   K2:   masked softmax + P@V            (SIMT)  -> g_att
//   K3:   out = att @ wout + bias         (HMMA, transposed store)
// ===========================================================================

#define HW_   8448
#define NROWS 84480

__device__ __align__(16) float g_qkv[(size_t)NROWS * 768];
__device__ __align__(16) float g_att[(size_t)NROWS * 256];
__device__ __align__(16) __nv_bfloat16 g_w1h[6 * 4 * 64 * 136];
__device__ __align__(16) __nv_bfloat16 g_w1l[6 * 4 * 64 * 136];
__device__ __align__(16) __nv_bfloat16 g_w2h[2 * 4 * 64 * 136];
__device__ __align__(16) __nv_bfloat16 g_w2l[2 * 4 * 64 * 136];

#define AP 264            // A smem pitch (bf16 elems): 528B ≡ 4 banks mod 32
#define BP 136            // B smem pitch: 272B ≡ 4 banks mod 32

// ----------------------------- helpers ------------------------------------
__device__ __forceinline__ uint32_t smem_u32(const void* p) {
    uint32_t a;
    asm("{ .reg .u64 t; cvta.to.shared.u64 t, %1; cvt.u32.u64 %0, t; }" : "=r"(a) : "l"(p));
    return a;
}
__device__ __forceinline__ float bres(float f) {
    return f - __bfloat162float(__float2bfloat16(f));
}
__device__ __forceinline__ uint64_t pack4(float a0, float a1, float a2, float a3) {
    uint64_t r = (uint64_t)__bfloat16_as_ushort(__float2bfloat16(a0));
    r |= (uint64_t)__bfloat16_as_ushort(__float2bfloat16(a1)) << 16;
    r |= (uint64_t)__bfloat16_as_ushort(__float2bfloat16(a2)) << 32;
    r |= (uint64_t)__bfloat16_as_ushort(__float2bfloat16(a3)) << 48;
    return r;
}
__device__ __forceinline__ void ldmA(uint32_t* r, uint32_t addr) {
    asm volatile("ldmatrix.sync.aligned.m8n8.x4.shared.b16 {%0,%1,%2,%3}, [%4];"
                 : "=r"(r[0]), "=r"(r[1]), "=r"(r[2]), "=r"(r[3]) : "r"(addr));
}
__device__ __forceinline__ void ldmB(uint32_t* r, uint32_t addr) {
    asm volatile("ldmatrix.sync.aligned.m8n8.x2.trans.shared.b16 {%0,%1}, [%2];"
                 : "=r"(r[0]), "=r"(r[1]) : "r"(addr));
}
__device__ __forceinline__ void mma16816(float* c, const uint32_t* a, const uint32_t* b) {
    asm volatile("mma.sync.aligned.m16n8k16.row.col.f32.bf16.bf16.f32 "
                 "{%0,%1,%2,%3}, {%4,%5,%6,%7}, {%8,%9}, {%0,%1,%2,%3};"
                 : "+f"(c[0]), "+f"(c[1]), "+f"(c[2]), "+f"(c[3])
                 : "r"(a[0]), "r"(a[1]), "r"(a[2]), "r"(a[3]), "r"(b[0]), "r"(b[1]));
}

// 3-pass mma over one 64-deep K chunk. acc[4][4][4] = warp tile 64x32.
// aHi/aLo: lane-adjusted base addrs of A[wm + (lane&15)][kc*64 + ((lane>>4)<<3)]
// bHi/bLo: lane-adjusted base addrs of B[lane&15][wn]
__device__ __forceinline__ void mma_chunk(float acc[4][4][4],
                                          uint32_t aHi, uint32_t aLo,
                                          uint32_t bHi, uint32_t bLo) {
    #pragma unroll
    for (int pass = 0; pass < 3; ++pass) {
        uint32_t aB = (pass < 2) ? aHi : aLo;
        uint32_t bB = (pass == 1) ? bLo : bHi;
        #pragma unroll
        for (int ks = 0; ks < 4; ++ks) {
            uint32_t a[4][4], b[4][2];
            #pragma unroll
            for (int i = 0; i < 4; ++i)
                ldmA(a[i], aB + (uint32_t)((i * 16 * AP + ks * 16) * 2));
            #pragma unroll
            for (int j = 0; j < 4; ++j)
                ldmB(b[j], bB + (uint32_t)((ks * 16 * BP + j * 8) * 2));
            #pragma unroll
            for (int i = 0; i < 4; ++i)
                #pragma unroll
                for (int j = 0; j < 4; ++j)
                    mma16816(acc[i][j], a[i], b[j]);
        }
    }
}

// ======================= prep: weight conversion ===========================
__global__ __launch_bounds__(256) void prep_w(const float* __restrict__ wqkv,
                                              const float* __restrict__ wout) {
    int idx = blockIdx.x * 256 + threadIdx.x;
    if (idx < 196608) {                     // wqkv: nt<6, kc<4, kr<64, n<128
        int n = idx & 127, kr = (idx >> 7) & 63, kc = (idx >> 13) & 3, nt = idx >> 15;
        float f = wqkv[(kc * 64 + kr) * 768 + nt * 128 + n];
        int o = ((nt * 4 + kc) * 64 + kr) * 136 + n;
        g_w1h[o] = __float2bfloat16(f);
        g_w1l[o] = __float2bfloat16(bres(f));
    } else {                                // wout: nt<2
        int t = idx - 196608;
        int n = t & 127, kr = (t >> 7) & 63, kc = (t >> 13) & 3, nt = t >> 15;
        float f = wout[(kc * 64 + kr) * 256 + nt * 128 + n];
        int o = ((nt * 4 + kc) * 64 + kr) * 136 + n;
        g_w2h[o] = __float2bfloat16(f);
        g_w2l[o] = __float2bfloat16(bres(f));
    }
}

// ======================= K1: QKV GEMM ======================================
// smem: AHI 0 (67584B), ALO 67584, BHI 135168 (17408B), BLO 152576 -> 169984
#define K1_ALO 67584
#define K1_BHI 135168
#define K1_BLO 152576
#define K1_SMEM 169984

__global__ __launch_bounds__(256, 1) void k1_qkv(const float* __restrict__ x) {
    extern __shared__ __align__(16) char sm[];
    const uint32_t sb = smem_u32(sm);
    const int tid = threadIdx.x, lane = tid & 31, wid = tid >> 5;
    const int wm = (wid & 1) * 64, wn = (wid >> 1) * 32;
    const int m0 = blockIdx.x * 128;

    // stage A slab (transposed gather from x), hi/lo bf16
    for (int e = tid; e < 128 * 64; e += 256) {
        int row = e >> 6, k4 = (e & 63) << 2;
        int r = m0 + row, g = r / 5, l = r - g * 5, b = g / HW_, hw = g - b * HW_;
        const float4 v = *(const float4*)(x + ((size_t)((b * 5 + l) * HW_ + hw)) * 256 + k4);
        uint32_t off = (uint32_t)(row * AP + k4) * 2;
        *(uint64_t*)(sm + off) = pack4(v.x, v.y, v.z, v.w);
        *(uint64_t*)(sm + K1_ALO + off) = pack4(bres(v.x), bres(v.y), bres(v.z), bres(v.w));
    }

    const uint32_t aoff = (uint32_t)(((wm + (lane & 15)) * AP + ((lane >> 4) << 3)) * 2);
    const uint32_t boff = (uint32_t)(((lane & 15) * BP + wn) * 2);

    for (int nt = 0; nt < 6; ++nt) {
        float acc[4][4][4];
        #pragma unroll
        for (int i = 0; i < 4; ++i)
            #pragma unroll
            for (int j = 0; j < 4; ++j)
                #pragma unroll
                for (int q = 0; q < 4; ++q) acc[i][j][q] = 0.f;

        for (int kc = 0; kc < 4; ++kc) {
            __syncthreads();    // previous chunk consumed (and A staged on first pass)
            const uint4* srcH = (const uint4*)(g_w1h + (nt * 4 + kc) * 64 * 136);
            const uint4* srcL = (const uint4*)(g_w1l + (nt * 4 + kc) * 64 * 136);
            for (int e = tid; e < 1088; e += 256) {
                ((uint4*)(sm + K1_BHI))[e] = srcH[e];
                ((uint4*)(sm + K1_BLO))[e] = srcL[e];
            }
            __syncthreads();
            mma_chunk(acc,
                      sb + aoff + (uint32_t)(kc * 64 * 2),
                      sb + K1_ALO + aoff + (uint32_t)(kc * 64 * 2),
                      sb + K1_BHI + boff, sb + K1_BLO + boff);
        }

        // epilogue: fp32 to g_qkv
        #pragma unroll
        for (int i = 0; i < 4; ++i) {
            int row = m0 + wm + i * 16 + (lane >> 2);
            #pragma unroll
            for (int j = 0; j < 4; ++j) {
                int col = nt * 128 + wn + j * 8 + (lane & 3) * 2;
                float* p = g_qkv + (size_t)row * 768 + col;
                *(float2*)p = make_float2(acc[i][j][0], acc[i][j][1]);
                *(float2*)(p + 8 * 768) = make_float2(acc[i][j][2], acc[i][j][3]);
            }
        }
    }
}

// ======================= K2: masked softmax attention (SIMT) ===============
#define K2_STR 769
#define K2_SMEM (20 * K2_STR * 4 + 100 * 4 + 20 * 4)

__global__ __launch_bounds__(128) void k2_attn(const int* __restrict__ mask) {
    extern __shared__ __align__(16) float sl[];           // [20][769]
    float* sc = sl + 20 * K2_STR;                         // [4][25]
    int*   ms = (int*)(sc + 100);                         // [20]
    const int tid = threadIdx.x;
    const int r0 = blockIdx.x * 20;
    const int g0 = blockIdx.x * 4;

    for (int e = tid; e < 20; e += 128) ms[e] = mask[g0 * 5 + e];
    for (int e = tid; e < 20 * 192; e += 128) {
        int row = e / 192, c4 = (e % 192) * 4;
        const float4 v = *(const float4*)(g_qkv + (size_t)(r0 + row) * 768 + c4);
        float* d = sl + row * K2_STR + c4;
        d[0] = v.x; d[1] = v.y; d[2] = v.z; d[3] = v.w;
    }
    __syncthreads();

    const float scale = 0.17677669529663687f;
    for (int h = 0; h < 8; ++h) {
        const int hc = h * 32;
        if (tid < 100) {
            int g = tid / 25, rr = tid % 25, i = rr / 5, j = rr % 5;
            float s;
            if (ms[g * 5 + j] == 0) s = -1e30f;
            else {
                const float* q = sl + (g * 5 + i) * K2_STR + hc;
                const float* k = sl + (g * 5 + j) * K2_STR + 256 + hc;
                s = 0.f;
                #pragma unroll
                for (int d = 0; d < 32; ++d) s = fmaf(q[d], k[d], s);
                s *= scale;
            }
            sc[tid] = s;
        }
        __syncthreads();
        if (tid < 20) {
            float* r = sc + (tid / 5) * 25 + (tid % 5) * 5;
            float mx = r[0];
            #pragma unroll
            for (int j = 1; j < 5; ++j) mx = fmaxf(mx, r[j]);
            float ev[5], s = 0.f;
            #pragma unroll
            for (int j = 0; j < 5; ++j) { ev[j] = __expf(r[j] - mx); s += ev[j]; }
            float inv = 1.f / s;
            #pragma unroll
            for (int j = 0; j < 5; ++j) r[j] = ev[j] * inv;
        }
        __syncthreads();
        for (int e = tid; e < 20 * 32; e += 128) {
            int row = e >> 5, d = e & 31;
            int g = row / 5, i = row - g * 5;
            const float* p = sc + g * 25 + i * 5;
            const float* v = sl + (g * 5) * K2_STR + 512 + hc + d;
            float o = 0.f;
            #pragma unroll
            for (int j = 0; j < 5; ++j) o = fmaf(p[j], v[j * K2_STR], o);
            g_att[(size_t)(r0 + row) * 256 + hc + d] = o;
        }
        __syncthreads();
    }
}

// ======================= K3: output GEMM + bias + transposed store =========
#define K3_ALO 67584
#define K3_BHI 135168
#define K3_BLO 152576
#define K3_BIAS 169984
#define K3_SMEM 171008

__global__ __launch_bounds__(256, 1) void k3_out(const float* __restrict__ bout,
                                                 float* __restrict__ out) {
    extern __shared__ __align__(16) char sm[];
    const uint32_t sb = smem_u32(sm);
    const int tid = threadIdx.x, lane = tid & 31, wid = tid >> 5;
    const int wm = (wid & 1) * 64, wn = (wid >> 1) * 32;
    const int m0 = blockIdx.x * 128;

    if (tid < 256) ((float*)(sm + K3_BIAS))[tid] = bout[tid];

    for (int e = tid; e < 128 * 64; e += 256) {
        int row = e >> 6, k4 = (e & 63) << 2;
        const float4 v = *(const float4*)(g_att + (size_t)(m0 + row) * 256 + k4);
        uint32_t off = (uint32_t)(row * AP + k4) * 2;
        *(uint64_t*)(sm + off) = pack4(v.x, v.y, v.z, v.w);
        *(uint64_t*)(sm + K3_ALO + off) = pack4(bres(v.x), bres(v.y), bres(v.z), bres(v.w));
    }

    const uint32_t aoff = (uint32_t)(((wm + (lane & 15)) * AP + ((lane >> 4) << 3)) * 2);
    const uint32_t boff = (uint32_t)(((lane & 15) * BP + wn) * 2);
    const float* bias = (const float*)(sm + K3_BIAS);

    for (int nt = 0; nt < 2; ++nt) {
        float acc[4][4][4];
        #pragma unroll
        for (int i = 0; i < 4; ++i)
            #pragma unroll
            for (int j = 0; j < 4; ++j)
                #pragma unroll
                for (int q = 0; q < 4; ++q) acc[i][j][q] = 0.f;

        for (int kc = 0; kc < 4; ++kc) {
            __syncthreads();
            const uint4* srcH = (const uint4*)(g_w2h + (nt * 4 + kc) * 64 * 136);
            const uint4* srcL = (const uint4*)(g_w2l + (nt * 4 + kc) * 64 * 136);
            for (int e = tid; e < 1088; e += 256) {
                ((uint4*)(sm + K3_BHI))[e] = srcH[e];
                ((uint4*)(sm + K3_BLO))[e] = srcL[e];
            }
            __syncthreads();
            mma_chunk(acc,
                      sb + aoff + (uint32_t)(kc * 64 * 2),
                      sb + K3_ALO + aoff + (uint32_t)(kc * 64 * 2),
                      sb + K3_BHI + boff, sb + K3_BLO + boff);
        }

        // epilogue: bias + transposed store to out (B,L,H,W,C layout)
        #pragma unroll
        for (int i = 0; i < 4; ++i) {
            int r1 = m0 + wm + i * 16 + (lane >> 2);
            #pragma unroll
            for (int rr = 0; rr < 2; ++rr) {
                int r = r1 + rr * 8;
                int g = r / 5, l = r - g * 5, b = g / HW_, hw = g - b * HW_;
                float* dst = out + ((size_t)((b * 5 + l) * HW_ + hw)) * 256;
                #pragma unroll
                for (int j = 0; j < 4; ++j) {
                    int col = nt * 128 + wn + j * 8 + (lane & 3) * 2;
                    float2 o = make_float2(acc[i][j][2 * rr] + bias[col],
                                           acc[i][j][2 * rr + 1] + bias[col + 1]);
                    *(float2*)(dst + col) = o;
                }
            }
        }
    }
}

// ===========================================================================
extern "C" void kernel_launch(void* const* d_in, const int* in_sizes, int n_in,
                              void* d_out, int out_size) {
    const float* x    = (const float*)d_in[0];
    const int*   mask = (const int*)d_in[1];
    const float* wqkv = (const float*)d_in[2];
    const float* wout = (const float*)d_in[3];
    const float* bout = (const float*)d_in[4];
    float*       out  = (float*)d_out;

    cudaFuncSetAttribute(k1_qkv, cudaFuncAttributeMaxDynamicSharedMemorySize, K1_SMEM);
    cudaFuncSetAttribute(k2_attn, cudaFuncAttributeMaxDynamicSharedMemorySize, K2_SMEM);
    cudaFuncSetAttribute(k3_out, cudaFuncAttributeMaxDynamicSharedMemorySize, K3_SMEM);

    prep_w<<<1024, 256>>>(wqkv, wout);
    k1_qkv<<<660, 256, K1_SMEM>>>(x);
    k2_attn<<<4224, 128, K2_SMEM>>>(mask);
    k3_out<<<660, 256, K3_SMEM>>>(bout, out);
}

// round 6
// speedup vs baseline: 2.8340x; 1.3988x over previous
#include <cuda_runtime.h>
#include <cuda_bf16.h>
#include <stdint.h>

// ===========================================================================
// CavAttention via mma.sync bf16 hi/lo split precision (3 passes)
// Round 6: cp.async double-buffered B staging (copy/MMA overlap)
//   prep: wqkv/wout -> bf16 hi/lo global images (padded pitch 136)
//   K1:   qkv = xp @ wqkv                 (HMMA)  -> g_qkv
//   K2:   masked softmax + P@V            (SIMT)  -> g_att
//   K3:   out = att @ wout + bias         (HMMA, transposed store)
// ===========================================================================

#define HW_   8448
#define NROWS 84480

__device__ __align__(16) float g_qkv[(size_t)NROWS * 768];
__device__ __align__(16) float g_att[(size_t)NROWS * 256];
__device__ __align__(16) __nv_bfloat16 g_w1h[6 * 4 * 64 * 136];
__device__ __align__(16) __nv_bfloat16 g_w1l[6 * 4 * 64 * 136];
__device__ __align__(16) __nv_bfloat16 g_w2h[2 * 4 * 64 * 136];
__device__ __align__(16) __nv_bfloat16 g_w2l[2 * 4 * 64 * 136];

#define AP 264            // A smem pitch (bf16 elems): 528B ≡ 4 banks mod 32
#define BP 136            // B smem pitch: 272B ≡ 4 banks mod 32

#define CHUNK_B  17408                    // one 64x136 bf16 image (bytes)
#define BUF_B    (2 * CHUNK_B)            // hi + lo per chunk
// ----------------------------- helpers ------------------------------------
__device__ __forceinline__ uint32_t smem_u32(const void* p) {
    uint32_t a;
    asm("{ .reg .u64 t; cvta.to.shared.u64 t, %1; cvt.u32.u64 %0, t; }" : "=r"(a) : "l"(p));
    return a;
}
__device__ __forceinline__ float bres(float f) {
    return f - __bfloat162float(__float2bfloat16(f));
}
__device__ __forceinline__ uint64_t pack4(float a0, float a1, float a2, float a3) {
    uint64_t r = (uint64_t)__bfloat16_as_ushort(__float2bfloat16(a0));
    r |= (uint64_t)__bfloat16_as_ushort(__float2bfloat16(a1)) << 16;
    r |= (uint64_t)__bfloat16_as_ushort(__float2bfloat16(a2)) << 32;
    r |= (uint64_t)__bfloat16_as_ushort(__float2bfloat16(a3)) << 48;
    return r;
}
__device__ __forceinline__ void cpa16(uint32_t dst, const void* src) {
    asm volatile("cp.async.cg.shared.global [%0], [%1], 16;" :: "r"(dst), "l"(src));
}
#define CP_COMMIT() asm volatile("cp.async.commit_group;" ::: "memory")
#define CP_WAIT(n)  asm volatile("cp.async.wait_group %0;" :: "n"(n) : "memory")

__device__ __forceinline__ void ldmA(uint32_t* r, uint32_t addr) {
    asm volatile("ldmatrix.sync.aligned.m8n8.x4.shared.b16 {%0,%1,%2,%3}, [%4];"
                 : "=r"(r[0]), "=r"(r[1]), "=r"(r[2]), "=r"(r[3]) : "r"(addr));
}
__device__ __forceinline__ void ldmB(uint32_t* r, uint32_t addr) {
    asm volatile("ldmatrix.sync.aligned.m8n8.x2.trans.shared.b16 {%0,%1}, [%2];"
                 : "=r"(r[0]), "=r"(r[1]) : "r"(addr));
}
__device__ __forceinline__ void mma16816(float* c, const uint32_t* a, const uint32_t* b) {
    asm volatile("mma.sync.aligned.m16n8k16.row.col.f32.bf16.bf16.f32 "
                 "{%0,%1,%2,%3}, {%4,%5,%6,%7}, {%8,%9}, {%0,%1,%2,%3};"
                 : "+f"(c[0]), "+f"(c[1]), "+f"(c[2]), "+f"(c[3])
                 : "r"(a[0]), "r"(a[1]), "r"(a[2]), "r"(a[3]), "r"(b[0]), "r"(b[1]));
}

// 3-pass mma over one 64-deep K chunk. acc[4][4][4] = warp tile 64x32.
__device__ __forceinline__ void mma_chunk(float acc[4][4][4],
                                          uint32_t aHi, uint32_t aLo,
                                          uint32_t bHi, uint32_t bLo) {
    #pragma unroll
    for (int pass = 0; pass < 3; ++pass) {
        uint32_t aB = (pass < 2) ? aHi : aLo;
        uint32_t bB = (pass == 1) ? bLo : bHi;
        #pragma unroll
        for (int ks = 0; ks < 4; ++ks) {
            uint32_t a[4][4], b[4][2];
            #pragma unroll
            for (int i = 0; i < 4; ++i)
                ldmA(a[i], aB + (uint32_t)((i * 16 * AP + ks * 16) * 2));
            #pragma unroll
            for (int j = 0; j < 4; ++j)
                ldmB(b[j], bB + (uint32_t)((ks * 16 * BP + j * 8) * 2));
            #pragma unroll
            for (int i = 0; i < 4; ++i)
                #pragma unroll
                for (int j = 0; j < 4; ++j)
                    mma16816(acc[i][j], a[i], b[j]);
        }
    }
}

// issue one B chunk (hi+lo) via cp.async; 1088 uint4 per image
__device__ __forceinline__ void stage_B(uint32_t dst, const __nv_bfloat16* srcH,
                                        const __nv_bfloat16* srcL, int tid) {
    const char* sH = (const char*)srcH;
    const char* sL = (const char*)srcL;
    #pragma unroll
    for (int q = 0; q < 5; ++q) {              // ceil(1088/256)=5, guarded
        int e = tid + q * 256;
        if (e < 1088) {
            cpa16(dst + e * 16, sH + e * 16);
            cpa16(dst + CHUNK_B + e * 16, sL + e * 16);
        }
    }
    CP_COMMIT();
}

// ======================= prep: weight conversion ===========================
__global__ __launch_bounds__(256) void prep_w(const float* __restrict__ wqkv,
                                              const float* __restrict__ wout) {
    int idx = blockIdx.x * 256 + threadIdx.x;
    if (idx < 196608) {                     // wqkv: nt<6, kc<4, kr<64, n<128
        int n = idx & 127, kr = (idx >> 7) & 63, kc = (idx >> 13) & 3, nt = idx >> 15;
        float f = wqkv[(kc * 64 + kr) * 768 + nt * 128 + n];
        int o = ((nt * 4 + kc) * 64 + kr) * 136 + n;
        g_w1h[o] = __float2bfloat16(f);
        g_w1l[o] = __float2bfloat16(bres(f));
    } else {                                // wout: nt<2
        int t = idx - 196608;
        int n = t & 127, kr = (t >> 7) & 63, kc = (t >> 13) & 3, nt = t >> 15;
        float f = wout[(kc * 64 + kr) * 256 + nt * 128 + n];
        int o = ((nt * 4 + kc) * 64 + kr) * 136 + n;
        g_w2h[o] = __float2bfloat16(f);
        g_w2l[o] = __float2bfloat16(bres(f));
    }
}

// ======================= K1: QKV GEMM ======================================
// smem: AHI 0 (67584B), ALO 67584, Bring 135168 (2 x 34816) -> 204800
#define K_ALO  67584
#define K_BB   135168
#define K1_SMEM 204800

__global__ __launch_bounds__(256, 1) void k1_qkv(const float* __restrict__ x) {
    extern __shared__ __align__(16) char sm[];
    const uint32_t sb = smem_u32(sm);
    const int tid = threadIdx.x, lane = tid & 31, wid = tid >> 5;
    const int wm = (wid & 1) * 64, wn = (wid >> 1) * 32;
    const int m0 = blockIdx.x * 128;

    // prefetch chunk 0 immediately (overlaps with A staging below)
    stage_B(sb + K_BB, g_w1h, g_w1l, tid);

    // stage A slab (transposed gather from x), hi/lo bf16
    for (int e = tid; e < 128 * 64; e += 256) {
        int row = e >> 6, k4 = (e & 63) << 2;
        int r = m0 + row, g = r / 5, l = r - g * 5, b = g / HW_, hw = g - b * HW_;
        const float4 v = *(const float4*)(x + ((size_t)((b * 5 + l) * HW_ + hw)) * 256 + k4);
        uint32_t off = (uint32_t)(row * AP + k4) * 2;
        *(uint64_t*)(sm + off) = pack4(v.x, v.y, v.z, v.w);
        *(uint64_t*)(sm + K_ALO + off) = pack4(bres(v.x), bres(v.y), bres(v.z), bres(v.w));
    }

    const uint32_t aoff = (uint32_t)(((wm + (lane & 15)) * AP + ((lane >> 4) << 3)) * 2);
    const uint32_t boff = (uint32_t)(((lane & 15) * BP + wn) * 2);

    float acc[4][4][4];
    for (int c = 0; c < 24; ++c) {             // chunk c = (nt = c/4, kc = c%4)
        const int kc = c & 3;
        if (kc == 0) {
            #pragma unroll
            for (int i = 0; i < 4; ++i)
                #pragma unroll
                for (int j = 0; j < 4; ++j)
                    #pragma unroll
                    for (int q = 0; q < 4; ++q) acc[i][j][q] = 0.f;
        }
        if (c > 0) __syncthreads();            // mma(c-1) done -> buf (c+1)&1 free
        if (c + 1 < 24)
            stage_B(sb + K_BB + ((c + 1) & 1) * BUF_B,
                    g_w1h + (c + 1) * 8704, g_w1l + (c + 1) * 8704, tid);
        if (c + 1 < 24) { CP_WAIT(1); } else { CP_WAIT(0); }
        __syncthreads();                       // chunk c visible (+ A on c==0)

        uint32_t bb = sb + K_BB + (c & 1) * BUF_B;
        mma_chunk(acc,
                  sb + aoff + (uint32_t)(kc * 64 * 2),
                  sb + K_ALO + aoff + (uint32_t)(kc * 64 * 2),
                  bb + boff, bb + CHUNK_B + boff);

        if (kc == 3) {                         // epilogue for tile nt = c/4
            const int nt = c >> 2;
            #pragma unroll
            for (int i = 0; i < 4; ++i) {
                int row = m0 + wm + i * 16 + (lane >> 2);
                #pragma unroll
                for (int j = 0; j < 4; ++j) {
                    int col = nt * 128 + wn + j * 8 + (lane & 3) * 2;
                    float* p = g_qkv + (size_t)row * 768 + col;
                    *(float2*)p = make_float2(acc[i][j][0], acc[i][j][1]);
                    *(float2*)(p + 8 * 768) = make_float2(acc[i][j][2], acc[i][j][3]);
                }
            }
        }
    }
}

// ======================= K2: masked softmax attention (SIMT) ===============
#define K2_STR 769
#define K2_SMEM (20 * K2_STR * 4 + 100 * 4 + 20 * 4)

__global__ __launch_bounds__(128) void k2_attn(const int* __restrict__ mask) {
    extern __shared__ __align__(16) float sl[];           // [20][769]
    float* sc = sl + 20 * K2_STR;                         // [4][25]
    int*   ms = (int*)(sc + 100);                         // [20]
    const int tid = threadIdx.x;
    const int r0 = blockIdx.x * 20;
    const int g0 = blockIdx.x * 4;

    for (int e = tid; e < 20; e += 128) ms[e] = mask[g0 * 5 + e];
    for (int e = tid; e < 20 * 192; e += 128) {
        int row = e / 192, c4 = (e % 192) * 4;
        const float4 v = *(const float4*)(g_qkv + (size_t)(r0 + row) * 768 + c4);
        float* d = sl + row * K2_STR + c4;
        d[0] = v.x; d[1] = v.y; d[2] = v.z; d[3] = v.w;
    }
    __syncthreads();

    const float scale = 0.17677669529663687f;
    for (int h = 0; h < 8; ++h) {
        const int hc = h * 32;
        if (tid < 100) {
            int g = tid / 25, rr = tid % 25, i = rr / 5, j = rr % 5;
            float s;
            if (ms[g * 5 + j] == 0) s = -1e30f;
            else {
                const float* q = sl + (g * 5 + i) * K2_STR + hc;
                const float* k = sl + (g * 5 + j) * K2_STR + 256 + hc;
                s = 0.f;
                #pragma unroll
                for (int d = 0; d < 32; ++d) s = fmaf(q[d], k[d], s);
                s *= scale;
            }
            sc[tid] = s;
        }
        __syncthreads();
        if (tid < 20) {
            float* r = sc + (tid / 5) * 25 + (tid % 5) * 5;
            float mx = r[0];
            #pragma unroll
            for (int j = 1; j < 5; ++j) mx = fmaxf(mx, r[j]);
            float ev[5], s = 0.f;
            #pragma unroll
            for (int j = 0; j < 5; ++j) { ev[j] = __expf(r[j] - mx); s += ev[j]; }
            float inv = 1.f / s;
            #pragma unroll
            for (int j = 0; j < 5; ++j) r[j] = ev[j] * inv;
        }
        __syncthreads();
        for (int e = tid; e < 20 * 32; e += 128) {
            int row = e >> 5, d = e & 31;
            int g = row / 5, i = row - g * 5;
            const float* p = sc + g * 25 + i * 5;
            const float* v = sl + (g * 5) * K2_STR + 512 + hc + d;
            float o = 0.f;
            #pragma unroll
            for (int j = 0; j < 5; ++j) o = fmaf(p[j], v[j * K2_STR], o);
            g_att[(size_t)(r0 + row) * 256 + hc + d] = o;
        }
        __syncthreads();
    }
}

// ======================= K3: output GEMM + bias + transposed store =========
#define K3_BIAS 204800
#define K3_SMEM 205824

__global__ __launch_bounds__(256, 1) void k3_out(const float* __restrict__ bout,
                                                 float* __restrict__ out) {
    extern __shared__ __align__(16) char sm[];
    const uint32_t sb = smem_u32(sm);
    const int tid = threadIdx.x, lane = tid & 31, wid = tid >> 5;
    const int wm = (wid & 1) * 64, wn = (wid >> 1) * 32;
    const int m0 = blockIdx.x * 128;

    stage_B(sb + K_BB, g_w2h, g_w2l, tid);     // prefetch chunk 0

    if (tid < 256) ((float*)(sm + K3_BIAS))[tid] = bout[tid];

    for (int e = tid; e < 128 * 64; e += 256) {
        int row = e >> 6, k4 = (e & 63) << 2;
        const float4 v = *(const float4*)(g_att + (size_t)(m0 + row) * 256 + k4);
        uint32_t off = (uint32_t)(row * AP + k4) * 2;
        *(uint64_t*)(sm + off) = pack4(v.x, v.y, v.z, v.w);
        *(uint64_t*)(sm + K_ALO + off) = pack4(bres(v.x), bres(v.y), bres(v.z), bres(v.w));
    }

    const uint32_t aoff = (uint32_t)(((wm + (lane & 15)) * AP + ((lane >> 4) << 3)) * 2);
    const uint32_t boff = (uint32_t)(((lane & 15) * BP + wn) * 2);
    const float* bias = (const float*)(sm + K3_BIAS);

    float acc[4][4][4];
    for (int c = 0; c < 8; ++c) {              // chunk c = (nt = c/4, kc = c%4)
        const int kc = c & 3;
        if (kc == 0) {
            #pragma unroll
            for (int i = 0; i < 4; ++i)
                #pragma unroll
                for (int j = 0; j < 4; ++j)
                    #pragma unroll
                    for (int q = 0; q < 4; ++q) acc[i][j][q] = 0.f;
        }
        if (c > 0) __syncthreads();
        if (c + 1 < 8)
            stage_B(sb + K_BB + ((c + 1) & 1) * BUF_B,
                    g_w2h + (c + 1) * 8704, g_w2l + (c + 1) * 8704, tid);
        if (c + 1 < 8) { CP_WAIT(1); } else { CP_WAIT(0); }
        __syncthreads();

        uint32_t bb = sb + K_BB + (c & 1) * BUF_B;
        mma_chunk(acc,
                  sb + aoff + (uint32_t)(kc * 64 * 2),
                  sb + K_ALO + aoff + (uint32_t)(kc * 64 * 2),
                  bb + boff, bb + CHUNK_B + boff);

        if (kc == 3) {                         // epilogue for tile nt = c/4
            const int nt = c >> 2;
            #pragma unroll
            for (int i = 0; i < 4; ++i) {
                int r1 = m0 + wm + i * 16 + (lane >> 2);
                #pragma unroll
                for (int rr = 0; rr < 2; ++rr) {
                    int r = r1 + rr * 8;
                    int g = r / 5, l = r - g * 5, b = g / HW_, hw = g - b * HW_;
                    float* dst = out + ((size_t)((b * 5 + l) * HW_ + hw)) * 256;
                    #pragma unroll
                    for (int j = 0; j < 4; ++j) {
                        int col = nt * 128 + wn + j * 8 + (lane & 3) * 2;
                        float2 o = make_float2(acc[i][j][2 * rr] + bias[col],
                                               acc[i][j][2 * rr + 1] + bias[col + 1]);
                        *(float2*)(dst + col) = o;
                    }
                }
            }
        }
    }
}

// ===========================================================================
extern "C" void kernel_launch(void* const* d_in, const int* in_sizes, int n_in,
                              void* d_out, int out_size) {
    const float* x    = (const float*)d_in[0];
    const int*   mask = (const int*)d_in[1];
    const float* wqkv = (const float*)d_in[2];
    const float* wout = (const float*)d_in[3];
    const float* bout = (const float*)d_in[4];
    float*       out  = (float*)d_out;

    cudaFuncSetAttribute(k1_qkv, cudaFuncAttributeMaxDynamicSharedMemorySize, K1_SMEM);
    cudaFuncSetAttribute(k2_attn, cudaFuncAttributeMaxDynamicSharedMemorySize, K2_SMEM);
    cudaFuncSetAttribute(k3_out, cudaFuncAttributeMaxDynamicSharedMemorySize, K3_SMEM);

    prep_w<<<1024, 256>>>(wqkv, wout);
    k1_qkv<<<660, 256, K1_SMEM>>>(x);
    k2_attn<<<4224, 128, K2_SMEM>>>(mask);
    k3_out<<<660, 256, K3_SMEM>>>(bout, out);
}